// round 16
// baseline (speedup 1.0000x reference)
#include <cuda_runtime.h>
#include <cuda_bf16.h>
#include <cstdint>

#define HIDDEN    1024
#define HEADS     16
#define HEAD_DIM  64
#define BATCH     4
#define SEQ       1024
#define ROWS      (BATCH*SEQ)        // 4096
#define BETA_F    0.9f
#define CLAMP_F   1.0f
#define STATE_CAP_F 10.0f
#define PITCH     40                 // ushorts per smem row (80 B, bank-clean)

#define ARR_BYTES    (128*PITCH*2)   // 10240
#define STAGE_BYTES  (4*ARR_BYTES)   // 40960
#define SMEM_TOTAL_B (2*STAGE_BYTES) // 81920

// ---------------- scratch (static device arrays are allowed) ---------------
__device__ float g_q[ROWS*HIDDEN];
__device__ float g_k[ROWS*HIDDEN];
__device__ float g_v[ROWS*HIDDEN];
__device__ float g_state_scratch[BATCH*HEADS*HEAD_DIM*HEAD_DIM];
__device__ int   g_qkv_ctr[32];      // per 128-row tile: 24 = complete (8x * 3z)

// pre-split bf16 operands
__device__ __nv_bfloat16 g_Xhi[ROWS*HIDDEN],  g_Xlo[ROWS*HIDDEN];
__device__ __nv_bfloat16 g_Whi[4*HIDDEN*HIDDEN], g_Wlo[4*HIDDEN*HIDDEN]; // q,k,v,o
__device__ __nv_bfloat16 g_Ohi[ROWS*HIDDEN],  g_Olo[ROWS*HIDDEN];

// ---------------------------------------------------------------------------
#define MMA16816(d, a, b0, b1)                                              \
    asm volatile("mma.sync.aligned.m16n8k16.row.col.f32.bf16.bf16.f32 "     \
                 "{%0,%1,%2,%3}, {%4,%5,%6,%7}, {%8,%9}, {%0,%1,%2,%3};"    \
                 : "+f"((d)[0]), "+f"((d)[1]), "+f"((d)[2]), "+f"((d)[3])   \
                 : "r"((a)[0]), "r"((a)[1]), "r"((a)[2]), "r"((a)[3]),      \
                   "r"(b0), "r"(b1))

#define LDSM4(r, addr)                                                      \
    asm volatile("ldmatrix.sync.aligned.m8n8.x4.shared.b16 "                \
                 "{%0,%1,%2,%3}, [%4];"                                     \
                 : "=r"((r)[0]), "=r"((r)[1]), "=r"((r)[2]), "=r"((r)[3])   \
                 : "r"(addr))

#define CP16(dst, src)                                                      \
    asm volatile("cp.async.cg.shared.global [%0], [%1], 16;"                \
                 :: "r"(dst), "l"(src))
#define CP_COMMIT() asm volatile("cp.async.commit_group;")
#define CP_WAIT(n)  asm volatile("cp.async.wait_group %0;" :: "n"(n))

__device__ __forceinline__ void bf16_split1(float x, __nv_bfloat16& h,
                                            __nv_bfloat16& l)
{
    h = __float2bfloat16_rn(x);
    l = __float2bfloat16_rn(x - __bfloat162float(h));
}

// named barrier (id 1) scoped to the scan's 128 live threads
__device__ __forceinline__ void bar128() {
    asm volatile("bar.sync 1, 128;" ::: "memory");
}
__device__ __forceinline__ int bar128_or(int pred) {
    int res;
    asm volatile("{\n\t"
                 ".reg .pred p, q;\n\t"
                 "setp.ne.s32 p, %1, 0;\n\t"
                 "bar.red.or.pred q, 1, 128, p;\n\t"
                 "selp.s32 %0, 1, 0, q;\n\t"
                 "}" : "=r"(res) : "r"(pred) : "memory");
    return res;
}

// ---------------------------------------------------------------------------
// split fp32 -> bf16 hi/lo. z=0: X; z=1..4: Wq,Wk,Wv,Wo. Also zeroes the
// producer/consumer counters for this launch (graph replays re-run this).
// ---------------------------------------------------------------------------
__global__ __launch_bounds__(256) void split_kernel(
    const float* __restrict__ X,  const float* __restrict__ Wq,
    const float* __restrict__ Wk, const float* __restrict__ Wv,
    const float* __restrict__ Wo)
{
    const int z = blockIdx.z;
    if (z == 0 && blockIdx.x == 0 && threadIdx.x < 32)
        g_qkv_ctr[threadIdx.x] = 0;

    const float* src; __nv_bfloat16* hi; __nv_bfloat16* lo; int n8;
    if (z == 0) { src = X;  hi = g_Xhi; lo = g_Xlo; n8 = ROWS*HIDDEN/8; }
    else {
        const float* ws[4] = {Wq, Wk, Wv, Wo};
        src = ws[z-1];
        hi = g_Whi + (size_t)(z-1)*HIDDEN*HIDDEN;
        lo = g_Wlo + (size_t)(z-1)*HIDDEN*HIDDEN;
        n8 = HIDDEN*HIDDEN/8;
    }
    const int i = blockIdx.x * 256 + threadIdx.x;
    if (i >= n8) return;
    const float4* p = (const float4*)src + 2*(size_t)i;
    float4 x0 = p[0], x1 = p[1];
    __nv_bfloat16 h[8], l[8];
    bf16_split1(x0.x, h[0], l[0]); bf16_split1(x0.y, h[1], l[1]);
    bf16_split1(x0.z, h[2], l[2]); bf16_split1(x0.w, h[3], l[3]);
    bf16_split1(x1.x, h[4], l[4]); bf16_split1(x1.y, h[5], l[5]);
    bf16_split1(x1.z, h[6], l[6]); bf16_split1(x1.w, h[7], l[7]);
    *(uint4*)(hi + 8*(size_t)i) = *(uint4*)h;
    *(uint4*)(lo + 8*(size_t)i) = *(uint4*)l;
}

// ---------------------------------------------------------------------------
// bf16x3 tensor-core GEMM body (identical math to R12/R15).
// ---------------------------------------------------------------------------
__device__ __forceinline__ void gemm_bf16_body(
    const __nv_bfloat16* __restrict__ Ahi, const __nv_bfloat16* __restrict__ Alo,
    const __nv_bfloat16* __restrict__ Bhi, const __nv_bfloat16* __restrict__ Blo,
    const float* __restrict__ bias, float* __restrict__ C,
    int m0, int n0, bool norm)
{
    extern __shared__ unsigned short dynsm[];
    const int N = HIDDEN, K = HIDDEN;

    const int tid  = threadIdx.x;
    const int lane = tid & 31;
    const int warp = tid >> 5;
    const int wm   = warp & 3;
    const int wn   = warp >> 2;

    const int arow = tid >> 1;
    const int acol = (tid & 1) * 16;
    const size_t aoff0 = (size_t)(m0 + arow) * K + acol;
    const size_t boff0 = (size_t)(n0 + arow) * K + acol;
    const uint32_t smbase = (uint32_t)__cvta_generic_to_shared(dynsm);
    const uint32_t dst0   = smbase + (uint32_t)(arow * (PITCH*2) + (tid & 1) * 32);

    const int a_row_l = lane & 15;
    const int a_col_l = (lane >> 4) << 3;
    const int b_n_l   = ((lane >> 4) << 3) + (lane & 7);
    const int b_k_l   = ((lane >> 3) & 1) << 3;

    float acc[2][8][4];
#pragma unroll
    for (int mi = 0; mi < 2; mi++)
#pragma unroll
        for (int nj = 0; nj < 8; nj++)
#pragma unroll
            for (int r = 0; r < 4; r++) acc[mi][nj][r] = 0.f;

    {
        const uint32_t d = dst0;
        CP16(d + 0*ARR_BYTES,      Ahi + aoff0);
        CP16(d + 0*ARR_BYTES + 16, Ahi + aoff0 + 8);
        CP16(d + 1*ARR_BYTES,      Alo + aoff0);
        CP16(d + 1*ARR_BYTES + 16, Alo + aoff0 + 8);
        CP16(d + 2*ARR_BYTES,      Bhi + boff0);
        CP16(d + 2*ARR_BYTES + 16, Bhi + boff0 + 8);
        CP16(d + 3*ARR_BYTES,      Blo + boff0);
        CP16(d + 3*ARR_BYTES + 16, Blo + boff0 + 8);
        CP_COMMIT();
    }

    const int NT = K / 32;
    for (int it = 0; it < NT; it++) {
        const int cur = it & 1;
        const int nxt = cur ^ 1;
        const bool hn = (it + 1) < NT;

        if (hn) {
            const int k1 = (it + 1) * 32;
            const uint32_t d = dst0 + nxt * STAGE_BYTES;
            const size_t ao = aoff0 + k1;
            const size_t bo = boff0 + k1;
            CP16(d + 0*ARR_BYTES,      Ahi + ao);
            CP16(d + 0*ARR_BYTES + 16, Ahi + ao + 8);
            CP16(d + 1*ARR_BYTES,      Alo + ao);
            CP16(d + 1*ARR_BYTES + 16, Alo + ao + 8);
            CP16(d + 2*ARR_BYTES,      Bhi + bo);
            CP16(d + 2*ARR_BYTES + 16, Bhi + bo + 8);
            CP16(d + 3*ARR_BYTES,      Blo + bo);
            CP16(d + 3*ARR_BYTES + 16, Blo + bo + 8);
            CP_COMMIT();
            CP_WAIT(1);
        } else {
            CP_WAIT(0);
        }
        __syncthreads();

        const uint32_t stA_hi = smbase + cur*STAGE_BYTES + 0*ARR_BYTES;
        const uint32_t stA_lo = smbase + cur*STAGE_BYTES + 1*ARR_BYTES;
        const uint32_t stB_hi = smbase + cur*STAGE_BYTES + 2*ARR_BYTES;
        const uint32_t stB_lo = smbase + cur*STAGE_BYTES + 3*ARR_BYTES;

#pragma unroll
        for (int ks = 0; ks < 2; ks++) {
            const int koff = ks * 16;
            uint32_t afh[2][4], afl[2][4];
#pragma unroll
            for (int mi = 0; mi < 2; mi++) {
                const uint32_t off =
                    ((uint32_t)((wm*32 + mi*16 + a_row_l) * PITCH
                                + koff + a_col_l)) * 2u;
                LDSM4(afh[mi], stA_hi + off);
                LDSM4(afl[mi], stA_lo + off);
            }
#pragma unroll
            for (int jp = 0; jp < 4; jp++) {
                uint32_t bfh[4], bfl[4];
                const uint32_t off =
                    ((uint32_t)((wn*64 + jp*16 + b_n_l) * PITCH
                                + koff + b_k_l)) * 2u;
                LDSM4(bfh, stB_hi + off);
                LDSM4(bfl, stB_lo + off);
#pragma unroll
                for (int mi = 0; mi < 2; mi++) {
                    MMA16816(acc[mi][2*jp],   afh[mi], bfh[0], bfh[1]);
                    MMA16816(acc[mi][2*jp],   afh[mi], bfl[0], bfl[1]);
                    MMA16816(acc[mi][2*jp],   afl[mi], bfh[0], bfh[1]);
                    MMA16816(acc[mi][2*jp+1], afh[mi], bfh[2], bfh[3]);
                    MMA16816(acc[mi][2*jp+1], afh[mi], bfl[2], bfl[3]);
                    MMA16816(acc[mi][2*jp+1], afl[mi], bfh[2], bfh[3]);
                }
            }
        }
        __syncthreads();
    }

    const int qr = lane >> 2;
    const int qc = (lane & 3) * 2;

#pragma unroll
    for (int mi = 0; mi < 2; mi++) {
        float c[8][4];
#pragma unroll
        for (int nj = 0; nj < 8; nj++) {
            const float b0 = bias[n0 + wn*64 + nj*8 + qc];
            const float b1 = bias[n0 + wn*64 + nj*8 + qc + 1];
            c[nj][0] = acc[mi][nj][0] + b0;
            c[nj][1] = acc[mi][nj][1] + b1;
            c[nj][2] = acc[mi][nj][2] + b0;
            c[nj][3] = acc[mi][nj][3] + b1;
        }
        if (norm) {
            float ss0 = 0.f, ss1 = 0.f;
#pragma unroll
            for (int nj = 0; nj < 8; nj++) {
                ss0 += c[nj][0]*c[nj][0] + c[nj][1]*c[nj][1];
                ss1 += c[nj][2]*c[nj][2] + c[nj][3]*c[nj][3];
            }
            ss0 += __shfl_xor_sync(0xffffffffu, ss0, 1);
            ss0 += __shfl_xor_sync(0xffffffffu, ss0, 2);
            ss1 += __shfl_xor_sync(0xffffffffu, ss1, 1);
            ss1 += __shfl_xor_sync(0xffffffffu, ss1, 2);
            const float inv0 = 1.0f / fmaxf(sqrtf(ss0), 1e-12f);
            const float inv1 = 1.0f / fmaxf(sqrtf(ss1), 1e-12f);
#pragma unroll
            for (int nj = 0; nj < 8; nj++) {
                c[nj][0] *= inv0; c[nj][1] *= inv0;
                c[nj][2] *= inv1; c[nj][3] *= inv1;
            }
        }
        const int row_lo = m0 + wm*32 + mi*16 + qr;
#pragma unroll
        for (int nj = 0; nj < 8; nj++) {
            const int col = n0 + wn*64 + nj*8 + qc;
            float2 lo; lo.x = c[nj][0]; lo.y = c[nj][1];
            float2 hi; hi.x = c[nj][2]; hi.y = c[nj][3];
            *(float2*)(C + (size_t)row_lo       * N + col) = lo;
            *(float2*)(C + (size_t)(row_lo + 8) * N + col) = hi;
        }
    }
}

// ---------------------------------------------------------------------------
// Fused qkv-GEMM + scan. Grid = 832 blocks x 256 threads.
//   bid 0..63   : scan block for (b,h) = bid  (threads 128-255 exit; named
//                 barrier id 1 with count 128 replaces __syncthreads)
//   bid 64..831 : qkv GEMM block. u = bid-64; z = u%3 (q/k/v), x = (u/3)%8,
//                 ti = u/24; my = (ti%4)*8 + ti/4  (batch-interleaved token
//                 tiles so every batch's tile 0 lands in wave 1).
// GEMM blocks bump g_qkv_ctr[my] (24 = tile complete); scan blocks gate each
// 128-token tile on the counter (spin + nanosleep in t0, then bar128).
// Deadlock-free: scan blocks (64) < CTA slots (296) and have the lowest bids.
// ---------------------------------------------------------------------------
__device__ __forceinline__ float clip1(float x) {
    return fminf(fmaxf(x, -CLAMP_F), CLAMP_F);
}

__device__ __forceinline__ void wait_tile(int my, int tid) {
    if (tid == 0) {
        while (atomicAdd(&g_qkv_ctr[my], 0) < 24) __nanosleep(128);
        __threadfence();
    }
    bar128();
}

__global__ __launch_bounds__(256, 2) void fused_qkv_scan_kernel(
    const float* __restrict__ bq, const float* __restrict__ bk,
    const float* __restrict__ bv, float* __restrict__ state_out)
{
    const int bid = blockIdx.x;

    if (bid >= 64) {
        // ---------------- qkv GEMM role ----------------
        const int u  = bid - 64;
        const int z  = u % 3;
        const int x  = (u / 3) % 8;
        const int ti = u / 24;
        const int my = (ti & 3) * 8 + (ti >> 2);

        const __nv_bfloat16* Wh = g_Whi + (size_t)z*HIDDEN*HIDDEN;
        const __nv_bfloat16* Wl = g_Wlo + (size_t)z*HIDDEN*HIDDEN;
        const float* bias; float* out; bool norm;
        if (z == 0)      { bias = bq; out = g_q; norm = true;  }
        else if (z == 1) { bias = bk; out = g_k; norm = true;  }
        else             { bias = bv; out = g_v; norm = false; }

        gemm_bf16_body(g_Xhi, g_Xlo, Wh, Wl, bias, out,
                       my * 128, x * 128, norm);
        __syncthreads();                 // all epilogue stores issued CTA-wide
        if (threadIdx.x == 0) {
            __threadfence();             // make them GPU-visible
            atomicAdd(&g_qkv_ctr[my], 1);
        }
        return;
    }

    // ---------------- scan role (warpgroup-specialized, R15 schedule) ------
    const int tid = threadIdx.x;
    if (tid >= 128) return;              // 128 live threads; bar id 1 count 128

    __shared__ float ksh[8][HEAD_DIM];
    __shared__ float qsh[8][HEAD_DIM];
    __shared__ float dsh[2][HEAD_DIM];

    const int t  = tid & 63;
    const int g  = tid >> 6;             // 0 = column group, 1 = row group
    const int bh = bid;
    const int b  = bh >> 4;
    const size_t base = (size_t)b * SEQ * HIDDEN
                      + (size_t)(bh & 15) * HEAD_DIM + t;

    float S[64];
#pragma unroll
    for (int i = 0; i < 64; i++) S[i] = 0.f;

    wait_tile(b * 8, tid);               // token tile 0 of this batch

    if (g == 0) {
        ksh[0][t] = __ldcg(&g_k[base]);
        ksh[1][t] = __ldcg(&g_k[base + HIDDEN]);
        ksh[2][t] = __ldcg(&g_k[base + 2*HIDDEN]);
    } else {
        qsh[0][t] = __ldcg(&g_q[base]);
        qsh[1][t] = __ldcg(&g_q[base + HIDDEN]);
        qsh[2][t] = __ldcg(&g_q[base + 2*HIDDEN]);
    }
    float kA = (g == 0) ? __ldcg(&g_k[base + 3*HIDDEN])
                        : __ldcg(&g_q[base + 3*HIDDEN]);
    float vC  = __ldcg(&g_v[base]);
    float vQ1 = __ldcg(&g_v[base + HIDDEN]);
    float vQ2 = __ldcg(&g_v[base + 2*HIDDEN]);
    float vQ3 = __ldcg(&g_v[base + 3*HIDDEN]);

    float pA = 1.f, pB = 1.f;
    bar128();

    for (int s = 0; s < SEQ; s++) {
        // gate on the tile containing step s+4 before prefetching it
        float kN = 0.f, vN = 0.f;
        if (s + 4 < SEQ) {
            if (((s + 4) & 127) == 0)
                wait_tile(b * 8 + ((s + 4) >> 7), tid);
            const size_t b4 = base + (size_t)(s + 4) * HIDDEN;
            kN = (g == 0) ? __ldcg(&g_k[b4]) : __ldcg(&g_q[b4]);
            vN = __ldcg(&g_v[b4]);
        }

        int over = 0;
        if (g == 0) {
            // ---- g0: step s ----
            const float4* kc = (const float4*)&ksh[s & 7][0];
            float a0 = 0.f, a1 = 0.f, a2 = 0.f, a3 = 0.f;
#pragma unroll
            for (int cc = 0; cc < 16; cc++) {
                const float4 k4 = kc[cc];
                a0 += k4.x * S[cc*4+0];
                a1 += k4.y * S[cc*4+1];
                a2 += k4.z * S[cc*4+2];
                a3 += k4.w * S[cc*4+3];
            }
            const float vold = (a0 + a1) + (a2 + a3);
            const float bd   = BETA_F * clip1(vC - pA * vold);
            dsh[s & 1][t] = bd;
            float lmax = 0.f;
            if (pA == 1.f) {
#pragma unroll
                for (int cc = 0; cc < 16; cc++) {
                    const float4 k4 = kc[cc];
                    float x0=fmaf(bd,k4.x,S[cc*4+0]), x1=fmaf(bd,k4.y,S[cc*4+1]);
                    float x2=fmaf(bd,k4.z,S[cc*4+2]), x3=fmaf(bd,k4.w,S[cc*4+3]);
                    S[cc*4+0]=x0; S[cc*4+1]=x1; S[cc*4+2]=x2; S[cc*4+3]=x3;
                    lmax = fmaxf(lmax, fmaxf(fmaxf(fabsf(x0),fabsf(x1)),
                                             fmaxf(fabsf(x2),fabsf(x3))));
                }
            } else {
#pragma unroll
                for (int cc = 0; cc < 16; cc++) {
                    const float4 k4 = kc[cc];
                    float x0=fmaf(pA,S[cc*4+0],bd*k4.x), x1=fmaf(pA,S[cc*4+1],bd*k4.y);
                    float x2=fmaf(pA,S[cc*4+2],bd*k4.z), x3=fmaf(pA,S[cc*4+3],bd*k4.w);
                    S[cc*4+0]=x0; S[cc*4+1]=x1; S[cc*4+2]=x2; S[cc*4+3]=x3;
                    lmax = fmaxf(lmax, fmaxf(fmaxf(fabsf(x0),fabsf(x1)),
                                             fmaxf(fabsf(x2),fabsf(x3))));
                }
            }
            over = (lmax > STATE_CAP_F);
            if (s + 3 < SEQ) ksh[(s + 3) & 7][t] = kA;
        } else if (s >= 1) {
            // ---- g1: step m = s-1 ----
            const int m = s - 1;
            const float kt = ksh[m & 7][t];
            const float4* d4 = (const float4*)&dsh[m & 1][0];
            const float4* q4 = (const float4*)&qsh[m & 7][0];
            float o0 = 0.f, o1 = 0.f, o2 = 0.f, o3 = 0.f;
            if (pB == 1.f) {
#pragma unroll
                for (int cc = 0; cc < 16; cc++) {
                    const float4 dd = d4[cc];
                    float y0=fmaf(kt,dd.x,S[cc*4+0]), y1=fmaf(kt,dd.y,S[cc*4+1]);
                    float y2=fmaf(kt,dd.z,S[cc*4+2]), y3=fmaf(kt,dd.w,S[cc*4+3]);
                    S[cc*4+0]=y0; S[cc*4+1]=y1; S[cc*4+2]=y2; S[cc*4+3]=y3;
                    const float4 qq = q4[cc];
                    o0 += y0*qq.x; o1 += y1*qq.y;
                    o2 += y2*qq.z; o3 += y3*qq.w;
                }
            } else {
#pragma unroll
                for (int cc = 0; cc < 16; cc++) {
                    const float4 dd = d4[cc];
                    float y0=fmaf(pB,S[cc*4+0],kt*dd.x), y1=fmaf(pB,S[cc*4+1],kt*dd.y);
                    float y2=fmaf(pB,S[cc*4+2],kt*dd.z), y3=fmaf(pB,S[cc*4+3],kt*dd.w);
                    S[cc*4+0]=y0; S[cc*4+1]=y1; S[cc*4+2]=y2; S[cc*4+3]=y3;
                    const float4 qq = q4[cc];
                    o0 += y0*qq.x; o1 += y1*qq.y;
                    o2 += y2*qq.z; o3 += y3*qq.w;
                }
            }
            const float val = clip1(pA * ((o0 + o1) + (o2 + o3)));
            __nv_bfloat16 h, l;
            bf16_split1(val, h, l);
            const size_t idx = base + (size_t)m * HIDDEN;
            g_Ohi[idx] = h; g_Olo[idx] = l;
            if (s + 3 < SEQ) qsh[(s + 3) & 7][t] = kA;
        } else {
            if (s + 3 < SEQ) qsh[(s + 3) & 7][t] = kA;
        }

        const int overAll = bar128_or(over);                // one barrier/step
        const float pn = overAll ? 0.9f : 1.0f;
        pB = pA; pA = pn;

        kA = kN;
        vC = vQ1; vQ1 = vQ2; vQ2 = vQ3; vQ3 = vN;
    }

    if (g == 1) {
        // epilogue: step SEQ-1 row update + o
        const int m = SEQ - 1;
        const float kt = ksh[m & 7][t];
        const float4* d4 = (const float4*)&dsh[m & 1][0];
        const float4* q4 = (const float4*)&qsh[m & 7][0];
        float o0 = 0.f, o1 = 0.f, o2 = 0.f, o3 = 0.f;
#pragma unroll
        for (int cc = 0; cc < 16; cc++) {
            const float4 dd = d4[cc];
            float y0=fmaf(pB,S[cc*4+0],kt*dd.x), y1=fmaf(pB,S[cc*4+1],kt*dd.y);
            float y2=fmaf(pB,S[cc*4+2],kt*dd.z), y3=fmaf(pB,S[cc*4+3],kt*dd.w);
            const float4 qq = q4[cc];
            o0 += y0*qq.x; o1 += y1*qq.y;
            o2 += y2*qq.z; o3 += y3*qq.w;
        }
        const float val = clip1(pA * ((o0 + o1) + (o2 + o3)));
        __nv_bfloat16 h, l;
        bf16_split1(val, h, l);
        const size_t idx = base + (size_t)m * HIDDEN;
        g_Ohi[idx] = h; g_Olo[idx] = l;
    } else {
        float* sp = state_out + (size_t)bh * HEAD_DIM * HEAD_DIM + t;
#pragma unroll
        for (int d = 0; d < 64; d++)
            sp[d * HEAD_DIM] = pA * S[d];
    }
}

__global__ __launch_bounds__(256, 2) void gemm_bf16_out_kernel(
    const float* __restrict__ bo, float* __restrict__ C)
{
    gemm_bf16_body(g_Ohi, g_Olo,
                   g_Whi + (size_t)3*HIDDEN*HIDDEN,
                   g_Wlo + (size_t)3*HIDDEN*HIDDEN,
                   bo, C, blockIdx.y * 128, blockIdx.x * 128, false);
}

// ---------------------------------------------------------------------------
extern "C" void kernel_launch(void* const* d_in, const int* in_sizes, int n_in,
                              void* d_out, int out_size)
{
    (void)in_sizes; (void)n_in;
    const float* x  = (const float*)d_in[0];
    const float* Wq = (const float*)d_in[1];
    const float* bq = (const float*)d_in[2];
    const float* Wk = (const float*)d_in[3];
    const float* bk = (const float*)d_in[4];
    const float* Wv = (const float*)d_in[5];
    const float* bv = (const float*)d_in[6];
    const float* Wo = (const float*)d_in[7];
    const float* bo = (const float*)d_in[8];

    const int OUT_ELEMS   = ROWS * HIDDEN;
    const int STATE_ELEMS = BATCH * HEADS * HEAD_DIM * HEAD_DIM;

    float* state_out;
    if (out_size >= OUT_ELEMS + STATE_ELEMS) {
        state_out = (float*)d_out + OUT_ELEMS;
    } else {
        cudaGetSymbolAddress((void**)&state_out, g_state_scratch);
    }

    static bool attr_done = false;
    if (!attr_done) {
        cudaFuncSetAttribute(fused_qkv_scan_kernel,
                             cudaFuncAttributeMaxDynamicSharedMemorySize,
                             SMEM_TOTAL_B);
        cudaFuncSetAttribute(gemm_bf16_out_kernel,
                             cudaFuncAttributeMaxDynamicSharedMemorySize,
                             SMEM_TOTAL_B);
        attr_done = true;
    }

    // 0) pre-split X + weights; zero the tile counters
    dim3 gs(ROWS * HIDDEN / 8 / 256, 1, 5);
    split_kernel<<<gs, 256>>>(x, Wq, Wk, Wv, Wo);

    // 1) fused qkv GEMM + scan (scan blocks first -> resident from wave 1)
    fused_qkv_scan_kernel<<<64 + 768, 256, SMEM_TOTAL_B>>>(bq, bk, bv,
                                                           state_out);

    // 2) output projection -> d_out
    dim3 go(HIDDEN / 128, ROWS / 128);
    gemm_bf16_out_kernel<<<go, 256, SMEM_TOTAL_B>>>(bo, (float*)d_out);
}

// round 17
// speedup vs baseline: 1.5108x; 1.5108x over previous
#include <cuda_runtime.h>
#include <cuda_bf16.h>
#include <cstdint>

#define HIDDEN    1024
#define HEADS     16
#define HEAD_DIM  64
#define BATCH     4
#define SEQ       1024
#define ROWS      (BATCH*SEQ)        // 4096
#define BETA_F    0.9f
#define CLAMP_F   1.0f
#define STATE_CAP_F 10.0f
#define PITCH     40                 // ushorts per smem row (80 B, bank-clean)

#define ARR_BYTES    (128*PITCH*2)   // 10240
#define STAGE_BYTES  (4*ARR_BYTES)   // 40960
#define SMEM_TOTAL_B (2*STAGE_BYTES) // 81920

typedef unsigned long long u64;

// ---------------- scratch (static device arrays are allowed) ---------------
__device__ float g_q[ROWS*HIDDEN];
__device__ float g_k[ROWS*HIDDEN];
__device__ float g_v[ROWS*HIDDEN];
__device__ float g_state_scratch[BATCH*HEADS*HEAD_DIM*HEAD_DIM];

// pre-split bf16 operands
__device__ __nv_bfloat16 g_Xhi[ROWS*HIDDEN],  g_Xlo[ROWS*HIDDEN];
__device__ __nv_bfloat16 g_Whi[4*HIDDEN*HIDDEN], g_Wlo[4*HIDDEN*HIDDEN]; // q,k,v,o
__device__ __nv_bfloat16 g_Ohi[ROWS*HIDDEN],  g_Olo[ROWS*HIDDEN];

// ---------------------------------------------------------------------------
#define MMA16816(d, a, b0, b1)                                              \
    asm volatile("mma.sync.aligned.m16n8k16.row.col.f32.bf16.bf16.f32 "     \
                 "{%0,%1,%2,%3}, {%4,%5,%6,%7}, {%8,%9}, {%0,%1,%2,%3};"    \
                 : "+f"((d)[0]), "+f"((d)[1]), "+f"((d)[2]), "+f"((d)[3])   \
                 : "r"((a)[0]), "r"((a)[1]), "r"((a)[2]), "r"((a)[3]),      \
                   "r"(b0), "r"(b1))

#define LDSM4(r, addr)                                                      \
    asm volatile("ldmatrix.sync.aligned.m8n8.x4.shared.b16 "                \
                 "{%0,%1,%2,%3}, [%4];"                                     \
                 : "=r"((r)[0]), "=r"((r)[1]), "=r"((r)[2]), "=r"((r)[3])   \
                 : "r"(addr))

#define CP16(dst, src)                                                      \
    asm volatile("cp.async.cg.shared.global [%0], [%1], 16;"                \
                 :: "r"(dst), "l"(src))
#define CP_COMMIT() asm volatile("cp.async.commit_group;")
#define CP_WAIT(n)  asm volatile("cp.async.wait_group %0;" :: "n"(n))

// packed f32x2 ops (Blackwell): element-wise, rounding identical to scalar
#define FMA2(d, a, b, c)                                                    \
    asm("fma.rn.f32x2 %0, %1, %2, %3;" : "=l"(d) : "l"(a), "l"(b), "l"(c))
#define MUL2(d, a, b)                                                       \
    asm("mul.rn.f32x2 %0, %1, %2;" : "=l"(d) : "l"(a), "l"(b))

__device__ __forceinline__ u64 pack2(float lo, float hi) {
    u64 r;
    asm("mov.b64 %0, {%1, %2};" : "=l"(r) : "r"(__float_as_uint(lo)),
        "r"(__float_as_uint(hi)));
    return r;
}
__device__ __forceinline__ void unpack2(u64 v, float& lo, float& hi) {
    unsigned a, b;
    asm("mov.b64 {%0, %1}, %2;" : "=r"(a), "=r"(b) : "l"(v));
    lo = __uint_as_float(a); hi = __uint_as_float(b);
}

__device__ __forceinline__ void bf16_split1(float x, __nv_bfloat16& h,
                                            __nv_bfloat16& l)
{
    h = __float2bfloat16_rn(x);
    l = __float2bfloat16_rn(x - __bfloat162float(h));
}

// ---------------------------------------------------------------------------
// split fp32 -> bf16 hi/lo. z=0: X; z=1..4: Wq,Wk,Wv,Wo. 8 elems/thread.
// ---------------------------------------------------------------------------
__global__ __launch_bounds__(256) void split_kernel(
    const float* __restrict__ X,  const float* __restrict__ Wq,
    const float* __restrict__ Wk, const float* __restrict__ Wv,
    const float* __restrict__ Wo)
{
    const int z = blockIdx.z;
    const float* src; __nv_bfloat16* hi; __nv_bfloat16* lo; int n8;
    if (z == 0) { src = X;  hi = g_Xhi; lo = g_Xlo; n8 = ROWS*HIDDEN/8; }
    else {
        const float* ws[4] = {Wq, Wk, Wv, Wo};
        src = ws[z-1];
        hi = g_Whi + (size_t)(z-1)*HIDDEN*HIDDEN;
        lo = g_Wlo + (size_t)(z-1)*HIDDEN*HIDDEN;
        n8 = HIDDEN*HIDDEN/8;
    }
    const int i = blockIdx.x * 256 + threadIdx.x;
    if (i >= n8) return;
    const float4* p = (const float4*)src + 2*(size_t)i;
    float4 x0 = p[0], x1 = p[1];
    __nv_bfloat16 h[8], l[8];
    bf16_split1(x0.x, h[0], l[0]); bf16_split1(x0.y, h[1], l[1]);
    bf16_split1(x0.z, h[2], l[2]); bf16_split1(x0.w, h[3], l[3]);
    bf16_split1(x1.x, h[4], l[4]); bf16_split1(x1.y, h[5], l[5]);
    bf16_split1(x1.z, h[6], l[6]); bf16_split1(x1.w, h[7], l[7]);
    *(uint4*)(hi + 8*(size_t)i) = *(uint4*)h;
    *(uint4*)(lo + 8*(size_t)i) = *(uint4*)l;
}

// ---------------------------------------------------------------------------
// bf16x3 tensor-core GEMM (byte-identical to R12/R15).
// ---------------------------------------------------------------------------
__device__ __forceinline__ void gemm_bf16_body(
    const __nv_bfloat16* __restrict__ Ahi, const __nv_bfloat16* __restrict__ Alo,
    const __nv_bfloat16* __restrict__ Bhi, const __nv_bfloat16* __restrict__ Blo,
    const float* __restrict__ bias, float* __restrict__ C,
    int m0, int n0, bool norm)
{
    extern __shared__ unsigned short dynsm[];
    const int N = HIDDEN, K = HIDDEN;

    const int tid  = threadIdx.x;
    const int lane = tid & 31;
    const int warp = tid >> 5;
    const int wm   = warp & 3;
    const int wn   = warp >> 2;

    const int arow = tid >> 1;
    const int acol = (tid & 1) * 16;
    const size_t aoff0 = (size_t)(m0 + arow) * K + acol;
    const size_t boff0 = (size_t)(n0 + arow) * K + acol;
    const uint32_t smbase = (uint32_t)__cvta_generic_to_shared(dynsm);
    const uint32_t dst0   = smbase + (uint32_t)(arow * (PITCH*2) + (tid & 1) * 32);

    const int a_row_l = lane & 15;
    const int a_col_l = (lane >> 4) << 3;
    const int b_n_l   = ((lane >> 4) << 3) + (lane & 7);
    const int b_k_l   = ((lane >> 3) & 1) << 3;

    float acc[2][8][4];
#pragma unroll
    for (int mi = 0; mi < 2; mi++)
#pragma unroll
        for (int nj = 0; nj < 8; nj++)
#pragma unroll
            for (int r = 0; r < 4; r++) acc[mi][nj][r] = 0.f;

    {
        const uint32_t d = dst0;
        CP16(d + 0*ARR_BYTES,      Ahi + aoff0);
        CP16(d + 0*ARR_BYTES + 16, Ahi + aoff0 + 8);
        CP16(d + 1*ARR_BYTES,      Alo + aoff0);
        CP16(d + 1*ARR_BYTES + 16, Alo + aoff0 + 8);
        CP16(d + 2*ARR_BYTES,      Bhi + boff0);
        CP16(d + 2*ARR_BYTES + 16, Bhi + boff0 + 8);
        CP16(d + 3*ARR_BYTES,      Blo + boff0);
        CP16(d + 3*ARR_BYTES + 16, Blo + boff0 + 8);
        CP_COMMIT();
    }

    const int NT = K / 32;
    for (int it = 0; it < NT; it++) {
        const int cur = it & 1;
        const int nxt = cur ^ 1;
        const bool hn = (it + 1) < NT;

        if (hn) {
            const int k1 = (it + 1) * 32;
            const uint32_t d = dst0 + nxt * STAGE_BYTES;
            const size_t ao = aoff0 + k1;
            const size_t bo = boff0 + k1;
            CP16(d + 0*ARR_BYTES,      Ahi + ao);
            CP16(d + 0*ARR_BYTES + 16, Ahi + ao + 8);
            CP16(d + 1*ARR_BYTES,      Alo + ao);
            CP16(d + 1*ARR_BYTES + 16, Alo + ao + 8);
            CP16(d + 2*ARR_BYTES,      Bhi + bo);
            CP16(d + 2*ARR_BYTES + 16, Bhi + bo + 8);
            CP16(d + 3*ARR_BYTES,      Blo + bo);
            CP16(d + 3*ARR_BYTES + 16, Blo + bo + 8);
            CP_COMMIT();
            CP_WAIT(1);
        } else {
            CP_WAIT(0);
        }
        __syncthreads();

        const uint32_t stA_hi = smbase + cur*STAGE_BYTES + 0*ARR_BYTES;
        const uint32_t stA_lo = smbase + cur*STAGE_BYTES + 1*ARR_BYTES;
        const uint32_t stB_hi = smbase + cur*STAGE_BYTES + 2*ARR_BYTES;
        const uint32_t stB_lo = smbase + cur*STAGE_BYTES + 3*ARR_BYTES;

#pragma unroll
        for (int ks = 0; ks < 2; ks++) {
            const int koff = ks * 16;
            uint32_t afh[2][4], afl[2][4];
#pragma unroll
            for (int mi = 0; mi < 2; mi++) {
                const uint32_t off =
                    ((uint32_t)((wm*32 + mi*16 + a_row_l) * PITCH
                                + koff + a_col_l)) * 2u;
                LDSM4(afh[mi], stA_hi + off);
                LDSM4(afl[mi], stA_lo + off);
            }
#pragma unroll
            for (int jp = 0; jp < 4; jp++) {
                uint32_t bfh[4], bfl[4];
                const uint32_t off =
                    ((uint32_t)((wn*64 + jp*16 + b_n_l) * PITCH
                                + koff + b_k_l)) * 2u;
                LDSM4(bfh, stB_hi + off);
                LDSM4(bfl, stB_lo + off);
#pragma unroll
                for (int mi = 0; mi < 2; mi++) {
                    MMA16816(acc[mi][2*jp],   afh[mi], bfh[0], bfh[1]);
                    MMA16816(acc[mi][2*jp],   afh[mi], bfl[0], bfl[1]);
                    MMA16816(acc[mi][2*jp],   afl[mi], bfh[0], bfh[1]);
                    MMA16816(acc[mi][2*jp+1], afh[mi], bfh[2], bfh[3]);
                    MMA16816(acc[mi][2*jp+1], afh[mi], bfl[2], bfl[3]);
                    MMA16816(acc[mi][2*jp+1], afl[mi], bfh[2], bfh[3]);
                }
            }
        }
        __syncthreads();
    }

    const int qr = lane >> 2;
    const int qc = (lane & 3) * 2;

#pragma unroll
    for (int mi = 0; mi < 2; mi++) {
        float c[8][4];
#pragma unroll
        for (int nj = 0; nj < 8; nj++) {
            const float b0 = bias[n0 + wn*64 + nj*8 + qc];
            const float b1 = bias[n0 + wn*64 + nj*8 + qc + 1];
            c[nj][0] = acc[mi][nj][0] + b0;
            c[nj][1] = acc[mi][nj][1] + b1;
            c[nj][2] = acc[mi][nj][2] + b0;
            c[nj][3] = acc[mi][nj][3] + b1;
        }
        if (norm) {
            float ss0 = 0.f, ss1 = 0.f;
#pragma unroll
            for (int nj = 0; nj < 8; nj++) {
                ss0 += c[nj][0]*c[nj][0] + c[nj][1]*c[nj][1];
                ss1 += c[nj][2]*c[nj][2] + c[nj][3]*c[nj][3];
            }
            ss0 += __shfl_xor_sync(0xffffffffu, ss0, 1);
            ss0 += __shfl_xor_sync(0xffffffffu, ss0, 2);
            ss1 += __shfl_xor_sync(0xffffffffu, ss1, 1);
            ss1 += __shfl_xor_sync(0xffffffffu, ss1, 2);
            const float inv0 = 1.0f / fmaxf(sqrtf(ss0), 1e-12f);
            const float inv1 = 1.0f / fmaxf(sqrtf(ss1), 1e-12f);
#pragma unroll
            for (int nj = 0; nj < 8; nj++) {
                c[nj][0] *= inv0; c[nj][1] *= inv0;
                c[nj][2] *= inv1; c[nj][3] *= inv1;
            }
        }
        const int row_lo = m0 + wm*32 + mi*16 + qr;
#pragma unroll
        for (int nj = 0; nj < 8; nj++) {
            const int col = n0 + wn*64 + nj*8 + qc;
            float2 lo; lo.x = c[nj][0]; lo.y = c[nj][1];
            float2 hi; hi.x = c[nj][2]; hi.y = c[nj][3];
            *(float2*)(C + (size_t)row_lo       * N + col) = lo;
            *(float2*)(C + (size_t)(row_lo + 8) * N + col) = hi;
        }
    }
}

__global__ __launch_bounds__(256, 2) void gemm_bf16_qkv_kernel(
    const float* __restrict__ bq, const float* __restrict__ bk,
    const float* __restrict__ bv)
{
    const int z = blockIdx.z;
    const __nv_bfloat16* Wh = g_Whi + (size_t)z*HIDDEN*HIDDEN;
    const __nv_bfloat16* Wl = g_Wlo + (size_t)z*HIDDEN*HIDDEN;
    const float* bias; float* out; bool norm;
    if (z == 0)      { bias = bq; out = g_q; norm = true;  }
    else if (z == 1) { bias = bk; out = g_k; norm = true;  }
    else             { bias = bv; out = g_v; norm = false; }
    gemm_bf16_body(g_Xhi, g_Xlo, Wh, Wl, bias, out,
                   blockIdx.y * 128, blockIdx.x * 128, norm);
}

__global__ __launch_bounds__(256, 2) void gemm_bf16_out_kernel(
    const float* __restrict__ bo, float* __restrict__ C)
{
    gemm_bf16_body(g_Ohi, g_Olo,
                   g_Whi + (size_t)3*HIDDEN*HIDDEN,
                   g_Wlo + (size_t)3*HIDDEN*HIDDEN,
                   bo, C, blockIdx.y * 128, blockIdx.x * 128, false);
}

// ---------------------------------------------------------------------------
// Warpgroup-specialized, software-pipelined delta-rule scan (R15 schedule),
// with packed fma.rn.f32x2 math: state held as 32 x u64 (float pairs).
// g0 (threads 0-63) owns full column t; g1 (threads 64-127) owns full row t,
// running one step behind. One __syncthreads_or per slot.
// ---------------------------------------------------------------------------
__device__ __forceinline__ float clip1(float x) {
    return fminf(fmaxf(x, -CLAMP_F), CLAMP_F);
}

__global__ __launch_bounds__(128) void scan_kernel(float* __restrict__ state_out)
{
    __shared__ float ksh[8][HEAD_DIM];
    __shared__ float qsh[8][HEAD_DIM];
    __shared__ float dsh[2][HEAD_DIM];

    const int tid = threadIdx.x;
    const int t   = tid & 63;
    const int g   = tid >> 6;     // 0 = column group, 1 = row group
    const int bh  = blockIdx.x;
    const size_t base = (size_t)(bh >> 4) * SEQ * HIDDEN
                      + (size_t)(bh & 15) * HEAD_DIM + t;

    u64 S2[32];                   // pairs: S2[i] = (elem 2i, elem 2i+1)
#pragma unroll
    for (int i = 0; i < 32; i++) S2[i] = 0ull;   // (+0.f, +0.f)

    if (g == 0) {
        ksh[0][t] = g_k[base];
        ksh[1][t] = g_k[base + HIDDEN];
        ksh[2][t] = g_k[base + 2*HIDDEN];
    } else {
        qsh[0][t] = g_q[base];
        qsh[1][t] = g_q[base + HIDDEN];
        qsh[2][t] = g_q[base + 2*HIDDEN];
    }
    float kA = (g == 0) ? g_k[base + 3*HIDDEN] : g_q[base + 3*HIDDEN];
    float vC  = g_v[base];
    float vQ1 = g_v[base + HIDDEN];
    float vQ2 = g_v[base + 2*HIDDEN];
    float vQ3 = g_v[base + 3*HIDDEN];

    float pA = 1.f, pB = 1.f;
    __syncthreads();

    for (int s = 0; s < SEQ; s++) {
        float kN = 0.f, vN = 0.f;
        if (s + 4 < SEQ) {
            const size_t b4 = base + (size_t)(s + 4) * HIDDEN;
            kN = (g == 0) ? g_k[b4] : g_q[b4];
            vN = g_v[b4];
        }

        int over = 0;
        if (g == 0) {
            // ---- g0: step s ----
            const ulonglong2* kc2 = (const ulonglong2*)&ksh[s & 7][0];
            u64 a2[4] = {0ull, 0ull, 0ull, 0ull};
#pragma unroll
            for (int cc = 0; cc < 16; cc++) {
                const ulonglong2 kk = kc2[cc];
                FMA2(a2[(2*cc) & 3],   kk.x, S2[2*cc],   a2[(2*cc) & 3]);
                FMA2(a2[(2*cc+1) & 3], kk.y, S2[2*cc+1], a2[(2*cc+1) & 3]);
            }
            float l0,h0,l1,h1,l2,h2,l3,h3;
            unpack2(a2[0], l0, h0); unpack2(a2[1], l1, h1);
            unpack2(a2[2], l2, h2); unpack2(a2[3], l3, h3);
            const float vold = ((l0+h0) + (l1+h1)) + ((l2+h2) + (l3+h3));
            const float bd   = BETA_F * clip1(vC - pA * vold);
            dsh[s & 1][t] = bd;
            const u64 bd2 = pack2(bd, bd);
            float lm0 = 0.f, lm1 = 0.f;
            if (pA == 1.f) {
#pragma unroll
                for (int cc = 0; cc < 16; cc++) {
                    const ulonglong2 kk = kc2[cc];
                    FMA2(S2[2*cc],   bd2, kk.x, S2[2*cc]);
                    FMA2(S2[2*cc+1], bd2, kk.y, S2[2*cc+1]);
                    float xl, xh, yl, yh;
                    unpack2(S2[2*cc],   xl, xh);
                    unpack2(S2[2*cc+1], yl, yh);
                    lm0 = fmaxf(lm0, fmaxf(fabsf(xl), fabsf(xh)));
                    lm1 = fmaxf(lm1, fmaxf(fabsf(yl), fabsf(yh)));
                }
            } else {
                const u64 pA2 = pack2(pA, pA);
#pragma unroll
                for (int cc = 0; cc < 16; cc++) {
                    const ulonglong2 kk = kc2[cc];
                    u64 t0, t1;
                    MUL2(t0, bd2, kk.x);
                    MUL2(t1, bd2, kk.y);
                    FMA2(S2[2*cc],   pA2, S2[2*cc],   t0);
                    FMA2(S2[2*cc+1], pA2, S2[2*cc+1], t1);
                    float xl, xh, yl, yh;
                    unpack2(S2[2*cc],   xl, xh);
                    unpack2(S2[2*cc+1], yl, yh);
                    lm0 = fmaxf(lm0, fmaxf(fabsf(xl), fabsf(xh)));
                    lm1 = fmaxf(lm1, fmaxf(fabsf(yl), fabsf(yh)));
                }
            }
            over = (fmaxf(lm0, lm1) > STATE_CAP_F);
            if (s + 3 < SEQ) ksh[(s + 3) & 7][t] = kA;
        } else if (s >= 1) {
            // ---- g1: step m = s-1 ----
            const int m = s - 1;
            const float kt = ksh[m & 7][t];
            const u64 kt2 = pack2(kt, kt);
            const ulonglong2* d2 = (const ulonglong2*)&dsh[m & 1][0];
            const ulonglong2* q2 = (const ulonglong2*)&qsh[m & 7][0];
            u64 o2[4] = {0ull, 0ull, 0ull, 0ull};
            if (pB == 1.f) {
#pragma unroll
                for (int cc = 0; cc < 16; cc++) {
                    const ulonglong2 dd = d2[cc];
                    FMA2(S2[2*cc],   kt2, dd.x, S2[2*cc]);
                    FMA2(S2[2*cc+1], kt2, dd.y, S2[2*cc+1]);
                    const ulonglong2 qq = q2[cc];
                    FMA2(o2[(2*cc) & 3],   S2[2*cc],   qq.x, o2[(2*cc) & 3]);
                    FMA2(o2[(2*cc+1) & 3], S2[2*cc+1], qq.y, o2[(2*cc+1) & 3]);
                }
            } else {
                const u64 pB2 = pack2(pB, pB);
#pragma unroll
                for (int cc = 0; cc < 16; cc++) {
                    const ulonglong2 dd = d2[cc];
                    u64 t0, t1;
                    MUL2(t0, kt2, dd.x);
                    MUL2(t1, kt2, dd.y);
                    FMA2(S2[2*cc],   pB2, S2[2*cc],   t0);
                    FMA2(S2[2*cc+1], pB2, S2[2*cc+1], t1);
                    const ulonglong2 qq = q2[cc];
                    FMA2(o2[(2*cc) & 3],   S2[2*cc],   qq.x, o2[(2*cc) & 3]);
                    FMA2(o2[(2*cc+1) & 3], S2[2*cc+1], qq.y, o2[(2*cc+1) & 3]);
                }
            }
            float l0,h0,l1,h1,l2,h2,l3,h3;
            unpack2(o2[0], l0, h0); unpack2(o2[1], l1, h1);
            unpack2(o2[2], l2, h2); unpack2(o2[3], l3, h3);
            const float osum = ((l0+h0) + (l1+h1)) + ((l2+h2) + (l3+h3));
            const float val = clip1(pA * osum);
            __nv_bfloat16 h, l;
            bf16_split1(val, h, l);
            const size_t idx = base + (size_t)m * HIDDEN;
            g_Ohi[idx] = h; g_Olo[idx] = l;
            if (s + 3 < SEQ) qsh[(s + 3) & 7][t] = kA;
        } else {
            if (s + 3 < SEQ) qsh[(s + 3) & 7][t] = kA;
        }

        const int overAll = __syncthreads_or(over);         // the one barrier
        const float pn = overAll ? 0.9f : 1.0f;
        pB = pA; pA = pn;

        kA = kN;
        vC = vQ1; vQ1 = vQ2; vQ2 = vQ3; vQ3 = vN;
    }

    if (g == 1) {
        // epilogue: step SEQ-1 row update + o (fold pB, output scale pA)
        const int m = SEQ - 1;
        const float kt = ksh[m & 7][t];
        const u64 kt2 = pack2(kt, kt);
        const u64 pB2 = pack2(pB, pB);
        const ulonglong2* d2 = (const ulonglong2*)&dsh[m & 1][0];
        const ulonglong2* q2 = (const ulonglong2*)&qsh[m & 7][0];
        u64 o2[4] = {0ull, 0ull, 0ull, 0ull};
#pragma unroll
        for (int cc = 0; cc < 16; cc++) {
            const ulonglong2 dd = d2[cc];
            u64 t0, t1, y0, y1;
            MUL2(t0, kt2, dd.x);
            MUL2(t1, kt2, dd.y);
            FMA2(y0, pB2, S2[2*cc],   t0);
            FMA2(y1, pB2, S2[2*cc+1], t1);
            const ulonglong2 qq = q2[cc];
            FMA2(o2[(2*cc) & 3],   y0, qq.x, o2[(2*cc) & 3]);
            FMA2(o2[(2*cc+1) & 3], y1, qq.y, o2[(2*cc+1) & 3]);
        }
        float l0,h0,l1,h1,l2,h2,l3,h3;
        unpack2(o2[0], l0, h0); unpack2(o2[1], l1, h1);
        unpack2(o2[2], l2, h2); unpack2(o2[3], l3, h3);
        const float osum = ((l0+h0) + (l1+h1)) + ((l2+h2) + (l3+h3));
        const float val = clip1(pA * osum);
        __nv_bfloat16 h, l;
        bf16_split1(val, h, l);
        const size_t idx = base + (size_t)m * HIDDEN;
        g_Ohi[idx] = h; g_Olo[idx] = l;
    } else {
        // final true state = pA * raw Sc : state_out[b][h][d][e], column t
        float* sp = state_out + (size_t)bh * HEAD_DIM * HEAD_DIM + t;
#pragma unroll
        for (int cc = 0; cc < 32; cc++) {
            float lo, hi;
            unpack2(S2[cc], lo, hi);
            sp[(2*cc)     * HEAD_DIM] = pA * lo;
            sp[(2*cc + 1) * HEAD_DIM] = pA * hi;
        }
    }
}

// ---------------------------------------------------------------------------
extern "C" void kernel_launch(void* const* d_in, const int* in_sizes, int n_in,
                              void* d_out, int out_size)
{
    (void)in_sizes; (void)n_in;
    const float* x  = (const float*)d_in[0];
    const float* Wq = (const float*)d_in[1];
    const float* bq = (const float*)d_in[2];
    const float* Wk = (const float*)d_in[3];
    const float* bk = (const float*)d_in[4];
    const float* Wv = (const float*)d_in[5];
    const float* bv = (const float*)d_in[6];
    const float* Wo = (const float*)d_in[7];
    const float* bo = (const float*)d_in[8];

    const int OUT_ELEMS   = ROWS * HIDDEN;
    const int STATE_ELEMS = BATCH * HEADS * HEAD_DIM * HEAD_DIM;

    float* state_out;
    if (out_size >= OUT_ELEMS + STATE_ELEMS) {
        state_out = (float*)d_out + OUT_ELEMS;
    } else {
        cudaGetSymbolAddress((void**)&state_out, g_state_scratch);
    }

    static bool attr_done = false;
    if (!attr_done) {
        cudaFuncSetAttribute(gemm_bf16_qkv_kernel,
                             cudaFuncAttributeMaxDynamicSharedMemorySize,
                             SMEM_TOTAL_B);
        cudaFuncSetAttribute(gemm_bf16_out_kernel,
                             cudaFuncAttributeMaxDynamicSharedMemorySize,
                             SMEM_TOTAL_B);
        attr_done = true;
    }

    // 0) pre-split X and all four weights to bf16 hi/lo
    dim3 gs(ROWS * HIDDEN / 8 / 256, 1, 5);
    split_kernel<<<gs, 256>>>(x, Wq, Wk, Wv, Wo);

    // 1) QKV projections (tensor-core bf16x3, cp.async, 2 CTAs/SM) + norm
    dim3 gq(HIDDEN / 128, ROWS / 128, 3);
    gemm_bf16_qkv_kernel<<<gq, 256, SMEM_TOTAL_B>>>(bq, bk, bv);

    // 2) warpgroup-specialized pipelined scan (f32x2 packed math)
    scan_kernel<<<BATCH * HEADS, 128>>>(state_out);

    // 3) output projection -> d_out
    dim3 go(HIDDEN / 128, ROWS / 128);
    gemm_bf16_out_kernel<<<go, 256, SMEM_TOTAL_B>>>(bo, (float*)d_out);
}